// round 9
// baseline (speedup 1.0000x reference)
#include <cuda_runtime.h>
#include <cuda_bf16.h>
#include <cstdint>

// ---------------------------------------------------------------------------
// GATNet, round 9:
//  - CSR-by-destination edge pipeline, deferred-W2 layer 2
//  - bf16x3 tensor GEMM (ldmatrix + cp.async) with FUSED alpha1 epilogue
//  - softmax fused into block-per-node aggregation kernels
//  - alpha2 fused into agg1 epilogue
// Output layout: [ out (N*64) | embeddings (N*128) ]
// ---------------------------------------------------------------------------

#define MAXN 100000
#define MAXE 600000
#define MAXET (MAXE + MAXN)
#define PAD 40
#define ECAP 1024   // smem edge capacity per node (deg ~7, Poisson; fallback exact)

// -------------------- scratch (device globals; no allocs) ------------------
__device__ float g_h1[(size_t)MAXN * 128];
__device__ float g_hact[(size_t)MAXN * 128];
__device__ float g_aggn[(size_t)MAXN * 512];
__device__ float g_as[(size_t)MAXN * 4];    // layer-1 alpha_src
__device__ float g_ad[(size_t)MAXN * 4];    // layer-1 alpha_dst
__device__ float g_as2[(size_t)MAXN * 4];   // layer-2 alpha_src
__device__ float g_ad2[(size_t)MAXN * 4];   // layer-2 alpha_dst
__device__ int   g_cnt[MAXN];
__device__ int   g_off[MAXN + 1];
__device__ int   g_bsum[1024];
__device__ int   g_csrc[MAXET];
__device__ __nv_bfloat16 g_W1h[128 * 512],  g_W1l[128 * 512];
__device__ __nv_bfloat16 g_W2h[128 * 512],  g_W2l[128 * 512];
__device__ __nv_bfloat16 g_WLh[64 * 128],   g_WLl[64 * 128];
__device__ float g_was[128 * 4], g_wad[128 * 4];

// -------------------- asm helpers -------------------------------------------
__device__ __forceinline__ void mma16816(float* c, const uint32_t* a, const uint32_t* b) {
    asm volatile(
        "mma.sync.aligned.m16n8k16.row.col.f32.bf16.bf16.f32 "
        "{%0,%1,%2,%3}, {%4,%5,%6,%7}, {%8,%9}, {%0,%1,%2,%3};\n"
        : "+f"(c[0]), "+f"(c[1]), "+f"(c[2]), "+f"(c[3])
        : "r"(a[0]), "r"(a[1]), "r"(a[2]), "r"(a[3]), "r"(b[0]), "r"(b[1]));
}
__device__ __forceinline__ uint32_t smem_u32(const void* p) {
    return (uint32_t)__cvta_generic_to_shared(p);
}
__device__ __forceinline__ void ldsm4(uint32_t& r0, uint32_t& r1, uint32_t& r2,
                                      uint32_t& r3, uint32_t a) {
    asm volatile("ldmatrix.sync.aligned.m8n8.x4.shared.b16 {%0,%1,%2,%3}, [%4];"
                 : "=r"(r0), "=r"(r1), "=r"(r2), "=r"(r3) : "r"(a));
}
__device__ __forceinline__ void cpa16(uint32_t dst, const void* src, int srcsz) {
    asm volatile("cp.async.cg.shared.global [%0], [%1], 16, %2;"
                 :: "r"(dst), "l"(src), "r"(srcsz));
}
__device__ __forceinline__ void cpa_commit() { asm volatile("cp.async.commit_group;"); }
__device__ __forceinline__ void cpa_wait0()  { asm volatile("cp.async.wait_group 0;" ::: "memory"); }

__device__ __forceinline__ float leaky(float v) { return v > 0.f ? v : 0.2f * v; }

// -------------------- tensor GEMM + optional fused alpha1 epilogue ----------
// C[M,N] = A[M,K] @ B[K,N] (+bias). If as1 != nullptr (layer-1 GEMM, N=128),
// also emits g_as/g_ad: per-(row,head) dots with a_src1/a_dst1 (flattened 128).
__global__ __launch_bounds__(256) void gemm_bf16x3(
    const float* __restrict__ A,
    const __nv_bfloat16* __restrict__ Bth, const __nv_bfloat16* __restrict__ Btl,
    const float* __restrict__ bias, float* __restrict__ C,
    int M, int N, int K,
    const float* __restrict__ as1, const float* __restrict__ ad1)
{
    __shared__ __align__(16) __nv_bfloat16 Ah[2][128][PAD];
    __shared__ __align__(16) __nv_bfloat16 Al[2][128][PAD];
    __shared__ __align__(16) __nv_bfloat16 Bh[2][128][PAD];
    __shared__ __align__(16) __nv_bfloat16 Bl[2][128][PAD];

    const int tid  = threadIdx.x;
    const int lane = tid & 31;
    const int wid  = tid >> 5;
    const int brow = blockIdx.y * 128;
    const int bcol = blockIdx.x * 128;
    const int moff = (wid >> 2) * 64;
    const int noff = (wid & 3) * 32;

    float acc[4][4][4];
#pragma unroll
    for (int i = 0; i < 4; i++)
#pragma unroll
        for (int j = 0; j < 4; j++)
#pragma unroll
            for (int q = 0; q < 4; q++) acc[i][j][q] = 0.f;

    const int ar  = tid >> 1;
    const int ac  = (tid & 1) * 16;
    const int agr = min(brow + ar, M - 1);
    const float* aptr = A + (size_t)agr * K + ac;
    const int bn  = tid >> 1;
    const int bk  = (tid & 1) * 16;
    const bool bvalid = (bcol + bn) < N;
    const int bsz = bvalid ? 16 : 0;
    const int bnc = bvalid ? (bcol + bn) : 0;
    const __nv_bfloat16* bph0 = Bth + (size_t)bnc * K + bk;
    const __nv_bfloat16* bpl0 = Btl + (size_t)bnc * K + bk;

    const int lr = lane & 7;
    const int lj = lane >> 3;
    const int a_ro = ((lj & 1) << 3) + lr;
    const int a_co = ((lj >> 1) << 3);
    const int b_ro = ((lj >> 1) << 3) + lr;
    const int b_co = ((lj & 1) << 3);

    float4 avr[4];

    avr[0] = reinterpret_cast<const float4*>(aptr)[0];
    avr[1] = reinterpret_cast<const float4*>(aptr)[1];
    avr[2] = reinterpret_cast<const float4*>(aptr)[2];
    avr[3] = reinterpret_cast<const float4*>(aptr)[3];
    {
        uint32_t dh = smem_u32(&Bh[0][bn][bk]);
        uint32_t dl = smem_u32(&Bl[0][bn][bk]);
        cpa16(dh, bph0, bsz);      cpa16(dh + 16, bph0 + 8, bsz);
        cpa16(dl, bpl0, bsz);      cpa16(dl + 16, bpl0 + 8, bsz);
        cpa_commit();
    }
    {
        float av[16] = {avr[0].x, avr[0].y, avr[0].z, avr[0].w,
                        avr[1].x, avr[1].y, avr[1].z, avr[1].w,
                        avr[2].x, avr[2].y, avr[2].z, avr[2].w,
                        avr[3].x, avr[3].y, avr[3].z, avr[3].w};
        __nv_bfloat16 hb[16], lb[16];
#pragma unroll
        for (int i = 0; i < 16; i++) {
            hb[i] = __float2bfloat16(av[i]);
            lb[i] = __float2bfloat16(av[i] - __bfloat162float(hb[i]));
        }
        *reinterpret_cast<uint4*>(&Ah[0][ar][ac])     = *reinterpret_cast<uint4*>(hb);
        *reinterpret_cast<uint4*>(&Ah[0][ar][ac + 8]) = *reinterpret_cast<uint4*>(hb + 8);
        *reinterpret_cast<uint4*>(&Al[0][ar][ac])     = *reinterpret_cast<uint4*>(lb);
        *reinterpret_cast<uint4*>(&Al[0][ar][ac + 8]) = *reinterpret_cast<uint4*>(lb + 8);
    }
    cpa_wait0();
    __syncthreads();

    int p = 0;
    for (int k0 = 0; k0 < K; k0 += 32) {
        const bool nxt = (k0 + 32) < K;
        if (nxt) {
            const float* ap = aptr + k0 + 32;
            avr[0] = reinterpret_cast<const float4*>(ap)[0];
            avr[1] = reinterpret_cast<const float4*>(ap)[1];
            avr[2] = reinterpret_cast<const float4*>(ap)[2];
            avr[3] = reinterpret_cast<const float4*>(ap)[3];
            uint32_t dh = smem_u32(&Bh[p ^ 1][bn][bk]);
            uint32_t dl = smem_u32(&Bl[p ^ 1][bn][bk]);
            const __nv_bfloat16* bph = bph0 + k0 + 32;
            const __nv_bfloat16* bpl = bpl0 + k0 + 32;
            cpa16(dh, bph, bsz);      cpa16(dh + 16, bph + 8, bsz);
            cpa16(dl, bpl, bsz);      cpa16(dl + 16, bpl + 8, bsz);
            cpa_commit();
        }

#pragma unroll
        for (int ks = 0; ks < 32; ks += 16) {
            uint32_t bhf[4][2], blf[4][2];
            {
                uint32_t a0 = smem_u32(&Bh[p][noff + b_ro][ks + b_co]);
                uint32_t a1 = smem_u32(&Bh[p][noff + 16 + b_ro][ks + b_co]);
                uint32_t a2 = smem_u32(&Bl[p][noff + b_ro][ks + b_co]);
                uint32_t a3 = smem_u32(&Bl[p][noff + 16 + b_ro][ks + b_co]);
                ldsm4(bhf[0][0], bhf[0][1], bhf[1][0], bhf[1][1], a0);
                ldsm4(bhf[2][0], bhf[2][1], bhf[3][0], bhf[3][1], a1);
                ldsm4(blf[0][0], blf[0][1], blf[1][0], blf[1][1], a2);
                ldsm4(blf[2][0], blf[2][1], blf[3][0], blf[3][1], a3);
            }
#pragma unroll
            for (int im = 0; im < 4; im++) {
                uint32_t ahf[4], alf[4];
                uint32_t aa  = smem_u32(&Ah[p][moff + im * 16 + a_ro][ks + a_co]);
                uint32_t al_ = smem_u32(&Al[p][moff + im * 16 + a_ro][ks + a_co]);
                ldsm4(ahf[0], ahf[1], ahf[2], ahf[3], aa);
                ldsm4(alf[0], alf[1], alf[2], alf[3], al_);
#pragma unroll
                for (int in = 0; in < 4; in++) {
                    mma16816(acc[im][in], ahf, bhf[in]);
                    mma16816(acc[im][in], ahf, blf[in]);
                    mma16816(acc[im][in], alf, bhf[in]);
                }
            }
        }

        if (nxt) {
            float av[16] = {avr[0].x, avr[0].y, avr[0].z, avr[0].w,
                            avr[1].x, avr[1].y, avr[1].z, avr[1].w,
                            avr[2].x, avr[2].y, avr[2].z, avr[2].w,
                            avr[3].x, avr[3].y, avr[3].z, avr[3].w};
            __nv_bfloat16 hb[16], lb[16];
#pragma unroll
            for (int i = 0; i < 16; i++) {
                hb[i] = __float2bfloat16(av[i]);
                lb[i] = __float2bfloat16(av[i] - __bfloat162float(hb[i]));
            }
            *reinterpret_cast<uint4*>(&Ah[p ^ 1][ar][ac])     = *reinterpret_cast<uint4*>(hb);
            *reinterpret_cast<uint4*>(&Ah[p ^ 1][ar][ac + 8]) = *reinterpret_cast<uint4*>(hb + 8);
            *reinterpret_cast<uint4*>(&Al[p ^ 1][ar][ac])     = *reinterpret_cast<uint4*>(lb);
            *reinterpret_cast<uint4*>(&Al[p ^ 1][ar][ac + 8]) = *reinterpret_cast<uint4*>(lb + 8);
            cpa_wait0();
        }
        __syncthreads();
        p ^= 1;
    }

    // ---- C epilogue ----
#pragma unroll
    for (int im = 0; im < 4; im++) {
#pragma unroll
        for (int in = 0; in < 4; in++) {
            int gr = brow + moff + im * 16 + (lane >> 2);
            int gc = bcol + noff + in * 8 + (lane & 3) * 2;
            if (gc >= N) continue;
            float bx = bias ? bias[gc] : 0.f;
            float by = bias ? bias[gc + 1] : 0.f;
            if (gr < M) {
                float2 v = make_float2(acc[im][in][0] + bx, acc[im][in][1] + by);
                *reinterpret_cast<float2*>(C + (size_t)gr * N + gc) = v;
            }
            if (gr + 8 < M) {
                float2 v = make_float2(acc[im][in][2] + bx, acc[im][in][3] + by);
                *reinterpret_cast<float2*>(C + (size_t)(gr + 8) * N + gc) = v;
            }
        }
    }

    // ---- fused alpha1 epilogue (layer-1 GEMM only; N==128, bcol==0) ----
    // Warp (wid&3) covers exactly head h = wid&3's 32 channels.
    if (as1) {
        const int head = wid & 3;
#pragma unroll
        for (int im = 0; im < 4; im++) {
            float s0 = 0.f, s1 = 0.f, d0 = 0.f, d1 = 0.f;
#pragma unroll
            for (int in = 0; in < 4; in++) {
                int gc = noff + in * 8 + (lane & 3) * 2;
                float a0 = as1[gc], a1 = as1[gc + 1];
                float e0 = ad1[gc], e1 = ad1[gc + 1];
                s0 += acc[im][in][0] * a0 + acc[im][in][1] * a1;
                s1 += acc[im][in][2] * a0 + acc[im][in][3] * a1;
                d0 += acc[im][in][0] * e0 + acc[im][in][1] * e1;
                d1 += acc[im][in][2] * e0 + acc[im][in][3] * e1;
            }
#pragma unroll
            for (int o = 1; o < 4; o <<= 1) {
                s0 += __shfl_xor_sync(0xFFFFFFFFu, s0, o);
                s1 += __shfl_xor_sync(0xFFFFFFFFu, s1, o);
                d0 += __shfl_xor_sync(0xFFFFFFFFu, d0, o);
                d1 += __shfl_xor_sync(0xFFFFFFFFu, d1, o);
            }
            if ((lane & 3) == 0) {
                int gr = brow + moff + im * 16 + (lane >> 2);
                if (gr < M)     { g_as[(size_t)gr * 4 + head] = s0; g_ad[(size_t)gr * 4 + head] = d0; }
                if (gr + 8 < M) { g_as[(size_t)(gr + 8) * 4 + head] = s1; g_ad[(size_t)(gr + 8) * 4 + head] = d1; }
            }
        }
    }
}

// -------------------- weight prep kernels ----------------------------------
__global__ void split_w(const float* __restrict__ W,
                        __nv_bfloat16* __restrict__ hi, __nv_bfloat16* __restrict__ lo,
                        int K, int N)
{
    int idx = blockIdx.x * blockDim.x + threadIdx.x;
    if (idx >= K * N) return;
    int k = idx / N, n = idx % N;
    float v = W[idx];
    __nv_bfloat16 h = __float2bfloat16(v);
    hi[(size_t)n * K + k] = h;
    lo[(size_t)n * K + k] = __float2bfloat16(v - __bfloat162float(h));
}
__global__ void split_w2p(const float* __restrict__ W2)
{
    int idx = blockIdx.x * blockDim.x + threadIdx.x;
    if (idx >= 512 * 128) return;
    int row = idx >> 7, c = idx & 127;
    int h = row >> 7, k = row & 127;
    float v = W2[(size_t)k * 512 + h * 128 + c];
    __nv_bfloat16 hb = __float2bfloat16(v);
    g_W2h[(size_t)c * 512 + row] = hb;
    g_W2l[(size_t)c * 512 + row] = __float2bfloat16(v - __bfloat162float(hb));
}
__global__ void build_wa(const float* __restrict__ W2,
                         const float* __restrict__ as2, const float* __restrict__ ad2)
{
    int gw   = (blockIdx.x * blockDim.x + threadIdx.x) >> 5;
    int lane = threadIdx.x & 31;
    if (gw >= 512) return;
    int k = gw >> 2, h = gw & 3;
    float ss = 0.f, sd = 0.f;
    for (int c = lane; c < 128; c += 32) {
        float w = W2[(size_t)k * 512 + h * 128 + c];
        ss = fmaf(w, as2[h * 128 + c], ss);
        sd = fmaf(w, ad2[h * 128 + c], sd);
    }
#pragma unroll
    for (int o = 16; o; o >>= 1) {
        ss += __shfl_xor_sync(0xFFFFFFFFu, ss, o);
        sd += __shfl_xor_sync(0xFFFFFFFFu, sd, o);
    }
    if (lane == 0) { g_was[k * 4 + h] = ss; g_wad[k * 4 + h] = sd; }
}

// -------------------- CSR build --------------------------------------------
__global__ void hist_k(const int* __restrict__ dst, int E, int N) {
    int e = blockIdx.x * blockDim.x + threadIdx.x;
    if (e >= E + N) return;
    int d = (e < E) ? dst[e] : e - E;
    atomicAdd(&g_cnt[d], 1);
}
__global__ __launch_bounds__(1024) void scan1(int N) {
    __shared__ int sh[1024];
    int i = blockIdx.x * 1024 + threadIdx.x;
    int v = (i < N) ? g_cnt[i] : 0;
    sh[threadIdx.x] = v;
    __syncthreads();
    for (int o = 1; o < 1024; o <<= 1) {
        int t = (threadIdx.x >= o) ? sh[threadIdx.x - o] : 0;
        __syncthreads();
        sh[threadIdx.x] += t;
        __syncthreads();
    }
    if (i < N) g_off[i] = sh[threadIdx.x] - v;
    if (threadIdx.x == 1023) g_bsum[blockIdx.x] = sh[1023];
}
__global__ __launch_bounds__(1024) void scan2(int NB) {
    __shared__ int sh[1024];
    int v = (threadIdx.x < NB) ? g_bsum[threadIdx.x] : 0;
    sh[threadIdx.x] = v;
    __syncthreads();
    for (int o = 1; o < 1024; o <<= 1) {
        int t = (threadIdx.x >= o) ? sh[threadIdx.x - o] : 0;
        __syncthreads();
        sh[threadIdx.x] += t;
        __syncthreads();
    }
    if (threadIdx.x < NB) g_bsum[threadIdx.x] = sh[threadIdx.x] - v;
}
__global__ void scan3(int N, int Et) {
    int i = blockIdx.x * blockDim.x + threadIdx.x;
    if (i < N) {
        int v = g_off[i] + g_bsum[i >> 10];
        g_off[i] = v;
        g_cnt[i] = v;
    }
    if (i == 0) g_off[N] = Et;
}
__global__ void scatter_k(const int* __restrict__ src, const int* __restrict__ dst,
                          int E, int N) {
    int e = blockIdx.x * blockDim.x + threadIdx.x;
    if (e >= E + N) return;
    int s, d;
    if (e < E) { s = src[e]; d = dst[e]; } else { s = d = e - E; }
    int p = atomicAdd(&g_cnt[d], 1);
    g_csrc[p] = s;
}

// -------------------- fused softmax + aggregation, layer 1 ------------------
// One block (128 threads) per node: softmax over incoming edges (smem-cached),
// aggregate h1, normalize + bias + ELU, write hact, then fused alpha2.
__global__ __launch_bounds__(128) void agg1f(const float* __restrict__ b1, int N)
{
    __shared__ float4 al[ECAP];
    __shared__ int    cs[ECAP];
    __shared__ float  red[4][8];
    __shared__ float  bc[8];

    int n = blockIdx.x;
    int tid = threadIdx.x, lane = tid & 31, wid = tid >> 5;
    int beg = g_off[n], end = g_off[n + 1], deg = end - beg;
    float4 D = *reinterpret_cast<const float4*>(g_ad + (size_t)n * 4);

    // pass 1: logits + per-head max
    float m0 = -1e30f, m1 = -1e30f, m2 = -1e30f, m3 = -1e30f;
    for (int idx = tid; idx < deg; idx += 128) {
        int s = g_csrc[beg + idx];
        float4 A = *reinterpret_cast<const float4*>(g_as + (size_t)s * 4);
        float v0 = leaky(A.x + D.x), v1 = leaky(A.y + D.y);
        float v2 = leaky(A.z + D.z), v3 = leaky(A.w + D.w);
        if (idx < ECAP) { al[idx] = make_float4(v0, v1, v2, v3); cs[idx] = s; }
        m0 = fmaxf(m0, v0); m1 = fmaxf(m1, v1);
        m2 = fmaxf(m2, v2); m3 = fmaxf(m3, v3);
    }
#pragma unroll
    for (int o = 16; o; o >>= 1) {
        m0 = fmaxf(m0, __shfl_xor_sync(0xFFFFFFFFu, m0, o));
        m1 = fmaxf(m1, __shfl_xor_sync(0xFFFFFFFFu, m1, o));
        m2 = fmaxf(m2, __shfl_xor_sync(0xFFFFFFFFu, m2, o));
        m3 = fmaxf(m3, __shfl_xor_sync(0xFFFFFFFFu, m3, o));
    }
    if (lane == 0) { red[wid][0] = m0; red[wid][1] = m1; red[wid][2] = m2; red[wid][3] = m3; }
    __syncthreads();
    if (tid < 4)
        bc[tid] = fmaxf(fmaxf(red[0][tid], red[1][tid]), fmaxf(red[2][tid], red[3][tid]));
    __syncthreads();
    m0 = bc[0]; m1 = bc[1]; m2 = bc[2]; m3 = bc[3];

    // pass 2: exp + per-head sum
    float s0 = 0.f, s1 = 0.f, s2 = 0.f, s3 = 0.f;
    for (int idx = tid; idx < deg; idx += 128) {
        float4 v;
        if (idx < ECAP) v = al[idx];
        else {
            int s = g_csrc[beg + idx];
            float4 A = *reinterpret_cast<const float4*>(g_as + (size_t)s * 4);
            v = make_float4(leaky(A.x + D.x), leaky(A.y + D.y),
                            leaky(A.z + D.z), leaky(A.w + D.w));
        }
        float e0 = expf(v.x - m0), e1 = expf(v.y - m1);
        float e2 = expf(v.z - m2), e3 = expf(v.w - m3);
        if (idx < ECAP) al[idx] = make_float4(e0, e1, e2, e3);
        s0 += e0; s1 += e1; s2 += e2; s3 += e3;
    }
#pragma unroll
    for (int o = 16; o; o >>= 1) {
        s0 += __shfl_xor_sync(0xFFFFFFFFu, s0, o);
        s1 += __shfl_xor_sync(0xFFFFFFFFu, s1, o);
        s2 += __shfl_xor_sync(0xFFFFFFFFu, s2, o);
        s3 += __shfl_xor_sync(0xFFFFFFFFu, s3, o);
    }
    __syncthreads();   // protect red reuse
    if (lane == 0) { red[wid][0] = s0; red[wid][1] = s1; red[wid][2] = s2; red[wid][3] = s3; }
    __syncthreads();
    if (tid < 4)
        bc[4 + tid] = 1.f / (red[0][tid] + red[1][tid] + red[2][tid] + red[3][tid] + 1e-16f);
    __syncthreads();

    // aggregation: thread c = feature, head h = c>>5
    int c = tid, h = c >> 5;
    float rh = bc[4 + h];
    float mh = (h == 0) ? m0 : (h == 1) ? m1 : (h == 2) ? m2 : m3;
    float Dh = (h == 0) ? D.x : (h == 1) ? D.y : (h == 2) ? D.z : D.w;
    float acc = 0.f;
    for (int j = 0; j < deg; j++) {
        int s; float w;
        if (j < ECAP) {
            s = cs[j];
            float4 e = al[j];
            w = (h == 0) ? e.x : (h == 1) ? e.y : (h == 2) ? e.z : e.w;
        } else {
            s = g_csrc[beg + j];
            float lv = leaky(g_as[(size_t)s * 4 + h] + Dh);
            w = expf(lv - mh);
        }
        acc = fmaf(w, g_h1[(size_t)s * 128 + c], acc);
    }
    float v = acc * rh + b1[c];
    v = v > 0.f ? v : expm1f(v);
    g_hact[(size_t)n * 128 + c] = v;

    // fused alpha2: dots of hact[n] with was/wad columns
    float4 ws = *reinterpret_cast<const float4*>(&g_was[c * 4]);
    float4 wd = *reinterpret_cast<const float4*>(&g_wad[c * 4]);
    float p0 = v * ws.x, p1 = v * ws.y, p2 = v * ws.z, p3 = v * ws.w;
    float q0 = v * wd.x, q1 = v * wd.y, q2 = v * wd.z, q3 = v * wd.w;
#pragma unroll
    for (int o = 16; o; o >>= 1) {
        p0 += __shfl_xor_sync(0xFFFFFFFFu, p0, o);
        p1 += __shfl_xor_sync(0xFFFFFFFFu, p1, o);
        p2 += __shfl_xor_sync(0xFFFFFFFFu, p2, o);
        p3 += __shfl_xor_sync(0xFFFFFFFFu, p3, o);
        q0 += __shfl_xor_sync(0xFFFFFFFFu, q0, o);
        q1 += __shfl_xor_sync(0xFFFFFFFFu, q1, o);
        q2 += __shfl_xor_sync(0xFFFFFFFFu, q2, o);
        q3 += __shfl_xor_sync(0xFFFFFFFFu, q3, o);
    }
    __syncthreads();   // protect red reuse
    if (lane == 0) {
        red[wid][0] = p0; red[wid][1] = p1; red[wid][2] = p2; red[wid][3] = p3;
        red[wid][4] = q0; red[wid][5] = q1; red[wid][6] = q2; red[wid][7] = q3;
    }
    __syncthreads();
    if (tid < 8) {
        float t = red[0][tid] + red[1][tid] + red[2][tid] + red[3][tid];
        if (tid < 4) g_as2[(size_t)n * 4 + tid] = t;
        else         g_ad2[(size_t)n * 4 + (tid - 4)] = t;
    }
}

// -------------------- fused softmax + aggregation, layer 2 ------------------
__global__ __launch_bounds__(128) void agg2f(int N)
{
    __shared__ float4 al[ECAP];
    __shared__ int    cs[ECAP];
    __shared__ float  red[4][4];
    __shared__ float  bc[8];

    int n = blockIdx.x;
    int tid = threadIdx.x, lane = tid & 31, wid = tid >> 5;
    int beg = g_off[n], end = g_off[n + 1], deg = end - beg;
    float4 D = *reinterpret_cast<const float4*>(g_ad2 + (size_t)n * 4);

    float m0 = -1e30f, m1 = -1e30f, m2 = -1e30f, m3 = -1e30f;
    for (int idx = tid; idx < deg; idx += 128) {
        int s = g_csrc[beg + idx];
        float4 A = *reinterpret_cast<const float4*>(g_as2 + (size_t)s * 4);
        float v0 = leaky(A.x + D.x), v1 = leaky(A.y + D.y);
        float v2 = leaky(A.z + D.z), v3 = leaky(A.w + D.w);
        if (idx < ECAP) { al[idx] = make_float4(v0, v1, v2, v3); cs[idx] = s; }
        m0 = fmaxf(m0, v0); m1 = fmaxf(m1, v1);
        m2 = fmaxf(m2, v2); m3 = fmaxf(m3, v3);
    }
#pragma unroll
    for (int o = 16; o; o >>= 1) {
        m0 = fmaxf(m0, __shfl_xor_sync(0xFFFFFFFFu, m0, o));
        m1 = fmaxf(m1, __shfl_xor_sync(0xFFFFFFFFu, m1, o));
        m2 = fmaxf(m2, __shfl_xor_sync(0xFFFFFFFFu, m2, o));
        m3 = fmaxf(m3, __shfl_xor_sync(0xFFFFFFFFu, m3, o));
    }
    if (lane == 0) { red[wid][0] = m0; red[wid][1] = m1; red[wid][2] = m2; red[wid][3] = m3; }
    __syncthreads();
    if (tid < 4)
        bc[tid] = fmaxf(fmaxf(red[0][tid], red[1][tid]), fmaxf(red[2][tid], red[3][tid]));
    __syncthreads();
    m0 = bc[0]; m1 = bc[1]; m2 = bc[2]; m3 = bc[3];

    float s0 = 0.f, s1 = 0.f, s2 = 0.f, s3 = 0.f;
    for (int idx = tid; idx < deg; idx += 128) {
        float4 v;
        if (idx < ECAP) v = al[idx];
        else {
            int s = g_csrc[beg + idx];
            float4 A = *reinterpret_cast<const float4*>(g_as2 + (size_t)s * 4);
            v = make_float4(leaky(A.x + D.x), leaky(A.y + D.y),
                            leaky(A.z + D.z), leaky(A.w + D.w));
        }
        float e0 = expf(v.x - m0), e1 = expf(v.y - m1);
        float e2 = expf(v.z - m2), e3 = expf(v.w - m3);
        if (idx < ECAP) al[idx] = make_float4(e0, e1, e2, e3);
        s0 += e0; s1 += e1; s2 += e2; s3 += e3;
    }
#pragma unroll
    for (int o = 16; o; o >>= 1) {
        s0 += __shfl_xor_sync(0xFFFFFFFFu, s0, o);
        s1 += __shfl_xor_sync(0xFFFFFFFFu, s1, o);
        s2 += __shfl_xor_sync(0xFFFFFFFFu, s2, o);
        s3 += __shfl_xor_sync(0xFFFFFFFFu, s3, o);
    }
    __syncthreads();
    if (lane == 0) { red[wid][0] = s0; red[wid][1] = s1; red[wid][2] = s2; red[wid][3] = s3; }
    __syncthreads();
    if (tid < 4)
        bc[4 + tid] = 0.25f / (red[0][tid] + red[1][tid] + red[2][tid] + red[3][tid] + 1e-16f);
    __syncthreads();

    // aggregation: thread k = feature channel within head block
    int k = tid;
    float r0 = bc[4], r1 = bc[5], r2 = bc[6], r3 = bc[7];
    float a0 = 0.f, a1 = 0.f, a2 = 0.f, a3 = 0.f;
    for (int j = 0; j < deg; j++) {
        int s; float4 e;
        if (j < ECAP) { s = cs[j]; e = al[j]; }
        else {
            s = g_csrc[beg + j];
            float4 A = *reinterpret_cast<const float4*>(g_as2 + (size_t)s * 4);
            e = make_float4(expf(leaky(A.x + D.x) - m0), expf(leaky(A.y + D.y) - m1),
                            expf(leaky(A.z + D.z) - m2), expf(leaky(A.w + D.w) - m3));
        }
        float v = g_hact[(size_t)s * 128 + k];
        a0 = fmaf(e.x, v, a0); a1 = fmaf(e.y, v, a1);
        a2 = fmaf(e.z, v, a2); a3 = fmaf(e.w, v, a3);
    }
    float* o = g_aggn + (size_t)n * 512;
    o[k]       = a0 * r0;
    o[128 + k] = a1 * r1;
    o[256 + k] = a2 * r2;
    o[384 + k] = a3 * r3;
}

// ---------------------------------------------------------------------------
extern "C" void kernel_launch(void* const* d_in, const int* in_sizes, int n_in,
                              void* d_out, int out_size)
{
    const float* x      = (const float*)d_in[0];
    const int*   eidx   = (const int*)d_in[1];
    const float* W1     = (const float*)d_in[2];
    const float* a_src1 = (const float*)d_in[3];
    const float* a_dst1 = (const float*)d_in[4];
    const float* b1     = (const float*)d_in[5];
    const float* W2     = (const float*)d_in[6];
    const float* a_src2 = (const float*)d_in[7];
    const float* a_dst2 = (const float*)d_in[8];
    const float* b2     = (const float*)d_in[9];
    const float* W_lin  = (const float*)d_in[10];
    const float* b_lin  = (const float*)d_in[11];

    const int N  = in_sizes[0] / 512;
    const int E  = in_sizes[1] / 2;
    const int Et = E + N;

    const int* src = eidx;
    const int* dst = eidx + E;

    float* out = (float*)d_out;
    float* emb = (float*)d_out + (size_t)N * 64;

    float* h1;   cudaGetSymbolAddress((void**)&h1,   g_h1);
    float* aggn; cudaGetSymbolAddress((void**)&aggn, g_aggn);
    int*   cnt;  cudaGetSymbolAddress((void**)&cnt,  g_cnt);
    __nv_bfloat16 *w1h, *w1l, *w2h, *w2l, *wlh, *wll;
    cudaGetSymbolAddress((void**)&w1h, g_W1h); cudaGetSymbolAddress((void**)&w1l, g_W1l);
    cudaGetSymbolAddress((void**)&w2h, g_W2h); cudaGetSymbolAddress((void**)&w2l, g_W2l);
    cudaGetSymbolAddress((void**)&wlh, g_WLh); cudaGetSymbolAddress((void**)&wll, g_WLl);

    const int T = 256;
    dim3 gg(1, (N + 127) / 128);

    int blk_e = (Et + T - 1) / T;
    int blk_n = (N + T - 1) / T;
    int NB    = (N + 1023) / 1024;

    // ---- CSR build ----
    cudaMemsetAsync(cnt, 0, (size_t)N * sizeof(int), 0);
    hist_k<<<blk_e, T>>>(dst, E, N);
    scan1<<<NB, 1024>>>(N);
    scan2<<<1, 1024>>>(NB);
    scan3<<<blk_n, T>>>(N, Et);
    scatter_k<<<blk_e, T>>>(src, dst, E, N);

    // ---- weight prep ----
    split_w<<<(512 * 128 + T - 1) / T, T>>>(W1, w1h, w1l, 512, 128);
    split_w2p<<<(512 * 128 + T - 1) / T, T>>>(W2);
    build_wa<<<64, T>>>(W2, a_src2, a_dst2);
    split_w<<<(128 * 64 + T - 1) / T, T>>>(W_lin, wlh, wll, 128, 64);

    // ---- layer 1: GEMM (+fused alpha1), fused softmax+agg (+fused alpha2) --
    gemm_bf16x3<<<gg, T>>>(x, w1h, w1l, nullptr, h1, N, 128, 512, a_src1, a_dst1);
    agg1f<<<N, 128>>>(b1, N);

    // ---- layer 2: fused softmax+agg, GEMM (deferred W2) ----
    agg2f<<<N, 128>>>(N);
    gemm_bf16x3<<<gg, T>>>(aggn, w2h, w2l, b2, emb, N, 128, 512, nullptr, nullptr);

    // ---- head ----
    gemm_bf16x3<<<gg, T>>>(emb, wlh, wll, b_lin, out, N, 64, 128, nullptr, nullptr);
}

// round 10
// speedup vs baseline: 1.4199x; 1.4199x over previous
#include <cuda_runtime.h>
#include <cuda_bf16.h>
#include <cstdint>

// ---------------------------------------------------------------------------
// GATNet, round 10:
//  - round-8 proven structure (CSR pipeline, warp-per-node softmax,
//    block-per-node gathers, deferred-W2 layer 2, bf16x3 tensor GEMM)
//  - fused alpha1 into GEMM1 epilogue (removes alpha_kernel)
//  - fused alpha2 into agg1_k epilogue (removes alpha2_kernel)
//  - cudaMemsetAsync replaces zero_cnt
// Output layout: [ out (N*64) | embeddings (N*128) ]
// ---------------------------------------------------------------------------

#define MAXN 100000
#define MAXE 600000
#define MAXET (MAXE + MAXN)
#define PAD 40

// -------------------- scratch (device globals; no allocs) ------------------
__device__ float g_h1[(size_t)MAXN * 128];
__device__ float g_hact[(size_t)MAXN * 128];
__device__ float g_aggn[(size_t)MAXN * 512];
__device__ float g_as[(size_t)MAXN * 4];    // layer-1 alpha_src
__device__ float g_ad[(size_t)MAXN * 4];    // layer-1 alpha_dst
__device__ float g_as2[(size_t)MAXN * 4];   // layer-2 alpha_src
__device__ float g_ad2[(size_t)MAXN * 4];   // layer-2 alpha_dst
__device__ float g_esum[(size_t)MAXN * 4];
__device__ int   g_cnt[MAXN];
__device__ int   g_off[MAXN + 1];
__device__ int   g_bsum[1024];
__device__ int   g_csrc[MAXET];
__device__ float g_alpha[(size_t)MAXET * 4];
__device__ __nv_bfloat16 g_W1h[128 * 512],  g_W1l[128 * 512];
__device__ __nv_bfloat16 g_W2h[128 * 512],  g_W2l[128 * 512];
__device__ __nv_bfloat16 g_WLh[64 * 128],   g_WLl[64 * 128];
__device__ float g_was[128 * 4], g_wad[128 * 4];

// -------------------- asm helpers -------------------------------------------
__device__ __forceinline__ void mma16816(float* c, const uint32_t* a, const uint32_t* b) {
    asm volatile(
        "mma.sync.aligned.m16n8k16.row.col.f32.bf16.bf16.f32 "
        "{%0,%1,%2,%3}, {%4,%5,%6,%7}, {%8,%9}, {%0,%1,%2,%3};\n"
        : "+f"(c[0]), "+f"(c[1]), "+f"(c[2]), "+f"(c[3])
        : "r"(a[0]), "r"(a[1]), "r"(a[2]), "r"(a[3]), "r"(b[0]), "r"(b[1]));
}
__device__ __forceinline__ uint32_t smem_u32(const void* p) {
    return (uint32_t)__cvta_generic_to_shared(p);
}
__device__ __forceinline__ void ldsm4(uint32_t& r0, uint32_t& r1, uint32_t& r2,
                                      uint32_t& r3, uint32_t a) {
    asm volatile("ldmatrix.sync.aligned.m8n8.x4.shared.b16 {%0,%1,%2,%3}, [%4];"
                 : "=r"(r0), "=r"(r1), "=r"(r2), "=r"(r3) : "r"(a));
}
__device__ __forceinline__ void cpa16(uint32_t dst, const void* src, int srcsz) {
    asm volatile("cp.async.cg.shared.global [%0], [%1], 16, %2;"
                 :: "r"(dst), "l"(src), "r"(srcsz));
}
__device__ __forceinline__ void cpa_commit() { asm volatile("cp.async.commit_group;"); }
__device__ __forceinline__ void cpa_wait0()  { asm volatile("cp.async.wait_group 0;" ::: "memory"); }

// -------------------- tensor GEMM + optional fused alpha1 epilogue ----------
__global__ __launch_bounds__(256) void gemm_bf16x3(
    const float* __restrict__ A,
    const __nv_bfloat16* __restrict__ Bth, const __nv_bfloat16* __restrict__ Btl,
    const float* __restrict__ bias, float* __restrict__ C,
    int M, int N, int K,
    const float* __restrict__ as1, const float* __restrict__ ad1)
{
    __shared__ __align__(16) __nv_bfloat16 Ah[2][128][PAD];
    __shared__ __align__(16) __nv_bfloat16 Al[2][128][PAD];
    __shared__ __align__(16) __nv_bfloat16 Bh[2][128][PAD];
    __shared__ __align__(16) __nv_bfloat16 Bl[2][128][PAD];

    const int tid  = threadIdx.x;
    const int lane = tid & 31;
    const int wid  = tid >> 5;
    const int brow = blockIdx.y * 128;
    const int bcol = blockIdx.x * 128;
    const int moff = (wid >> 2) * 64;
    const int noff = (wid & 3) * 32;

    float acc[4][4][4];
#pragma unroll
    for (int i = 0; i < 4; i++)
#pragma unroll
        for (int j = 0; j < 4; j++)
#pragma unroll
            for (int q = 0; q < 4; q++) acc[i][j][q] = 0.f;

    const int ar  = tid >> 1;
    const int ac  = (tid & 1) * 16;
    const int agr = min(brow + ar, M - 1);
    const float* aptr = A + (size_t)agr * K + ac;
    const int bn  = tid >> 1;
    const int bk  = (tid & 1) * 16;
    const bool bvalid = (bcol + bn) < N;
    const int bsz = bvalid ? 16 : 0;
    const int bnc = bvalid ? (bcol + bn) : 0;
    const __nv_bfloat16* bph0 = Bth + (size_t)bnc * K + bk;
    const __nv_bfloat16* bpl0 = Btl + (size_t)bnc * K + bk;

    const int lr = lane & 7;
    const int lj = lane >> 3;
    const int a_ro = ((lj & 1) << 3) + lr;
    const int a_co = ((lj >> 1) << 3);
    const int b_ro = ((lj >> 1) << 3) + lr;
    const int b_co = ((lj & 1) << 3);

    float4 avr[4];

    avr[0] = reinterpret_cast<const float4*>(aptr)[0];
    avr[1] = reinterpret_cast<const float4*>(aptr)[1];
    avr[2] = reinterpret_cast<const float4*>(aptr)[2];
    avr[3] = reinterpret_cast<const float4*>(aptr)[3];
    {
        uint32_t dh = smem_u32(&Bh[0][bn][bk]);
        uint32_t dl = smem_u32(&Bl[0][bn][bk]);
        cpa16(dh, bph0, bsz);      cpa16(dh + 16, bph0 + 8, bsz);
        cpa16(dl, bpl0, bsz);      cpa16(dl + 16, bpl0 + 8, bsz);
        cpa_commit();
    }
    {
        float av[16] = {avr[0].x, avr[0].y, avr[0].z, avr[0].w,
                        avr[1].x, avr[1].y, avr[1].z, avr[1].w,
                        avr[2].x, avr[2].y, avr[2].z, avr[2].w,
                        avr[3].x, avr[3].y, avr[3].z, avr[3].w};
        __nv_bfloat16 hb[16], lb[16];
#pragma unroll
        for (int i = 0; i < 16; i++) {
            hb[i] = __float2bfloat16(av[i]);
            lb[i] = __float2bfloat16(av[i] - __bfloat162float(hb[i]));
        }
        *reinterpret_cast<uint4*>(&Ah[0][ar][ac])     = *reinterpret_cast<uint4*>(hb);
        *reinterpret_cast<uint4*>(&Ah[0][ar][ac + 8]) = *reinterpret_cast<uint4*>(hb + 8);
        *reinterpret_cast<uint4*>(&Al[0][ar][ac])     = *reinterpret_cast<uint4*>(lb);
        *reinterpret_cast<uint4*>(&Al[0][ar][ac + 8]) = *reinterpret_cast<uint4*>(lb + 8);
    }
    cpa_wait0();
    __syncthreads();

    int p = 0;
    for (int k0 = 0; k0 < K; k0 += 32) {
        const bool nxt = (k0 + 32) < K;
        if (nxt) {
            const float* ap = aptr + k0 + 32;
            avr[0] = reinterpret_cast<const float4*>(ap)[0];
            avr[1] = reinterpret_cast<const float4*>(ap)[1];
            avr[2] = reinterpret_cast<const float4*>(ap)[2];
            avr[3] = reinterpret_cast<const float4*>(ap)[3];
            uint32_t dh = smem_u32(&Bh[p ^ 1][bn][bk]);
            uint32_t dl = smem_u32(&Bl[p ^ 1][bn][bk]);
            const __nv_bfloat16* bph = bph0 + k0 + 32;
            const __nv_bfloat16* bpl = bpl0 + k0 + 32;
            cpa16(dh, bph, bsz);      cpa16(dh + 16, bph + 8, bsz);
            cpa16(dl, bpl, bsz);      cpa16(dl + 16, bpl + 8, bsz);
            cpa_commit();
        }

#pragma unroll
        for (int ks = 0; ks < 32; ks += 16) {
            uint32_t bhf[4][2], blf[4][2];
            {
                uint32_t a0 = smem_u32(&Bh[p][noff + b_ro][ks + b_co]);
                uint32_t a1 = smem_u32(&Bh[p][noff + 16 + b_ro][ks + b_co]);
                uint32_t a2 = smem_u32(&Bl[p][noff + b_ro][ks + b_co]);
                uint32_t a3 = smem_u32(&Bl[p][noff + 16 + b_ro][ks + b_co]);
                ldsm4(bhf[0][0], bhf[0][1], bhf[1][0], bhf[1][1], a0);
                ldsm4(bhf[2][0], bhf[2][1], bhf[3][0], bhf[3][1], a1);
                ldsm4(blf[0][0], blf[0][1], blf[1][0], blf[1][1], a2);
                ldsm4(blf[2][0], blf[2][1], blf[3][0], blf[3][1], a3);
            }
#pragma unroll
            for (int im = 0; im < 4; im++) {
                uint32_t ahf[4], alf[4];
                uint32_t aa  = smem_u32(&Ah[p][moff + im * 16 + a_ro][ks + a_co]);
                uint32_t al_ = smem_u32(&Al[p][moff + im * 16 + a_ro][ks + a_co]);
                ldsm4(ahf[0], ahf[1], ahf[2], ahf[3], aa);
                ldsm4(alf[0], alf[1], alf[2], alf[3], al_);
#pragma unroll
                for (int in = 0; in < 4; in++) {
                    mma16816(acc[im][in], ahf, bhf[in]);
                    mma16816(acc[im][in], ahf, blf[in]);
                    mma16816(acc[im][in], alf, bhf[in]);
                }
            }
        }

        if (nxt) {
            float av[16] = {avr[0].x, avr[0].y, avr[0].z, avr[0].w,
                            avr[1].x, avr[1].y, avr[1].z, avr[1].w,
                            avr[2].x, avr[2].y, avr[2].z, avr[2].w,
                            avr[3].x, avr[3].y, avr[3].z, avr[3].w};
            __nv_bfloat16 hb[16], lb[16];
#pragma unroll
            for (int i = 0; i < 16; i++) {
                hb[i] = __float2bfloat16(av[i]);
                lb[i] = __float2bfloat16(av[i] - __bfloat162float(hb[i]));
            }
            *reinterpret_cast<uint4*>(&Ah[p ^ 1][ar][ac])     = *reinterpret_cast<uint4*>(hb);
            *reinterpret_cast<uint4*>(&Ah[p ^ 1][ar][ac + 8]) = *reinterpret_cast<uint4*>(hb + 8);
            *reinterpret_cast<uint4*>(&Al[p ^ 1][ar][ac])     = *reinterpret_cast<uint4*>(lb);
            *reinterpret_cast<uint4*>(&Al[p ^ 1][ar][ac + 8]) = *reinterpret_cast<uint4*>(lb + 8);
            cpa_wait0();
        }
        __syncthreads();
        p ^= 1;
    }

    // ---- C epilogue ----
#pragma unroll
    for (int im = 0; im < 4; im++) {
#pragma unroll
        for (int in = 0; in < 4; in++) {
            int gr = brow + moff + im * 16 + (lane >> 2);
            int gc = bcol + noff + in * 8 + (lane & 3) * 2;
            if (gc >= N) continue;
            float bx = bias ? bias[gc] : 0.f;
            float by = bias ? bias[gc + 1] : 0.f;
            if (gr < M) {
                float2 v = make_float2(acc[im][in][0] + bx, acc[im][in][1] + by);
                *reinterpret_cast<float2*>(C + (size_t)gr * N + gc) = v;
            }
            if (gr + 8 < M) {
                float2 v = make_float2(acc[im][in][2] + bx, acc[im][in][3] + by);
                *reinterpret_cast<float2*>(C + (size_t)(gr + 8) * N + gc) = v;
            }
        }
    }

    // ---- fused alpha1 epilogue (layer-1 GEMM only; N==128, bcol==0) ----
    if (as1) {
        const int head = wid & 3;
#pragma unroll
        for (int im = 0; im < 4; im++) {
            float s0 = 0.f, s1 = 0.f, d0 = 0.f, d1 = 0.f;
#pragma unroll
            for (int in = 0; in < 4; in++) {
                int gc = noff + in * 8 + (lane & 3) * 2;
                float a0 = as1[gc], a1 = as1[gc + 1];
                float e0 = ad1[gc], e1 = ad1[gc + 1];
                s0 += acc[im][in][0] * a0 + acc[im][in][1] * a1;
                s1 += acc[im][in][2] * a0 + acc[im][in][3] * a1;
                d0 += acc[im][in][0] * e0 + acc[im][in][1] * e1;
                d1 += acc[im][in][2] * e0 + acc[im][in][3] * e1;
            }
#pragma unroll
            for (int o = 1; o < 4; o <<= 1) {
                s0 += __shfl_xor_sync(0xFFFFFFFFu, s0, o);
                s1 += __shfl_xor_sync(0xFFFFFFFFu, s1, o);
                d0 += __shfl_xor_sync(0xFFFFFFFFu, d0, o);
                d1 += __shfl_xor_sync(0xFFFFFFFFu, d1, o);
            }
            if ((lane & 3) == 0) {
                int gr = brow + moff + im * 16 + (lane >> 2);
                if (gr < M)     { g_as[(size_t)gr * 4 + head] = s0; g_ad[(size_t)gr * 4 + head] = d0; }
                if (gr + 8 < M) { g_as[(size_t)(gr + 8) * 4 + head] = s1; g_ad[(size_t)(gr + 8) * 4 + head] = d1; }
            }
        }
    }
}

// -------------------- weight prep kernels ----------------------------------
__global__ void split_w(const float* __restrict__ W,
                        __nv_bfloat16* __restrict__ hi, __nv_bfloat16* __restrict__ lo,
                        int K, int N)
{
    int idx = blockIdx.x * blockDim.x + threadIdx.x;
    if (idx >= K * N) return;
    int k = idx / N, n = idx % N;
    float v = W[idx];
    __nv_bfloat16 h = __float2bfloat16(v);
    hi[(size_t)n * K + k] = h;
    lo[(size_t)n * K + k] = __float2bfloat16(v - __bfloat162float(h));
}
__global__ void split_w2p(const float* __restrict__ W2)
{
    int idx = blockIdx.x * blockDim.x + threadIdx.x;
    if (idx >= 512 * 128) return;
    int row = idx >> 7, c = idx & 127;
    int h = row >> 7, k = row & 127;
    float v = W2[(size_t)k * 512 + h * 128 + c];
    __nv_bfloat16 hb = __float2bfloat16(v);
    g_W2h[(size_t)c * 512 + row] = hb;
    g_W2l[(size_t)c * 512 + row] = __float2bfloat16(v - __bfloat162float(hb));
}
__global__ void build_wa(const float* __restrict__ W2,
                         const float* __restrict__ as2, const float* __restrict__ ad2)
{
    int gw   = (blockIdx.x * blockDim.x + threadIdx.x) >> 5;
    int lane = threadIdx.x & 31;
    if (gw >= 512) return;
    int k = gw >> 2, h = gw & 3;
    float ss = 0.f, sd = 0.f;
    for (int c = lane; c < 128; c += 32) {
        float w = W2[(size_t)k * 512 + h * 128 + c];
        ss = fmaf(w, as2[h * 128 + c], ss);
        sd = fmaf(w, ad2[h * 128 + c], sd);
    }
#pragma unroll
    for (int o = 16; o; o >>= 1) {
        ss += __shfl_xor_sync(0xFFFFFFFFu, ss, o);
        sd += __shfl_xor_sync(0xFFFFFFFFu, sd, o);
    }
    if (lane == 0) { g_was[k * 4 + h] = ss; g_wad[k * 4 + h] = sd; }
}

// -------------------- CSR build --------------------------------------------
__global__ void hist_k(const int* __restrict__ dst, int E, int N) {
    int e = blockIdx.x * blockDim.x + threadIdx.x;
    if (e >= E + N) return;
    int d = (e < E) ? dst[e] : e - E;
    atomicAdd(&g_cnt[d], 1);
}
__global__ __launch_bounds__(1024) void scan1(int N) {
    __shared__ int sh[1024];
    int i = blockIdx.x * 1024 + threadIdx.x;
    int v = (i < N) ? g_cnt[i] : 0;
    sh[threadIdx.x] = v;
    __syncthreads();
    for (int o = 1; o < 1024; o <<= 1) {
        int t = (threadIdx.x >= o) ? sh[threadIdx.x - o] : 0;
        __syncthreads();
        sh[threadIdx.x] += t;
        __syncthreads();
    }
    if (i < N) g_off[i] = sh[threadIdx.x] - v;
    if (threadIdx.x == 1023) g_bsum[blockIdx.x] = sh[1023];
}
__global__ __launch_bounds__(1024) void scan2(int NB) {
    __shared__ int sh[1024];
    int v = (threadIdx.x < NB) ? g_bsum[threadIdx.x] : 0;
    sh[threadIdx.x] = v;
    __syncthreads();
    for (int o = 1; o < 1024; o <<= 1) {
        int t = (threadIdx.x >= o) ? sh[threadIdx.x - o] : 0;
        __syncthreads();
        sh[threadIdx.x] += t;
        __syncthreads();
    }
    if (threadIdx.x < NB) g_bsum[threadIdx.x] = sh[threadIdx.x] - v;
}
__global__ void scan3(int N, int Et) {
    int i = blockIdx.x * blockDim.x + threadIdx.x;
    if (i < N) {
        int v = g_off[i] + g_bsum[i >> 10];
        g_off[i] = v;
        g_cnt[i] = v;
    }
    if (i == 0) g_off[N] = Et;
}
__global__ void scatter_k(const int* __restrict__ src, const int* __restrict__ dst,
                          int E, int N) {
    int e = blockIdx.x * blockDim.x + threadIdx.x;
    if (e >= E + N) return;
    int s, d;
    if (e < E) { s = src[e]; d = dst[e]; } else { s = d = e - E; }
    int p = atomicAdd(&g_cnt[d], 1);
    g_csrc[p] = s;
}

// -------------------- per-node warp softmax (parameterized alphas) ----------
__global__ void edge_softmax(const float* __restrict__ as,
                             const float* __restrict__ ad, int N)
{
    int gw   = (blockIdx.x * blockDim.x + threadIdx.x) >> 5;
    int lane = threadIdx.x & 31;
    if (gw >= N) return;
    int beg = g_off[gw], end = g_off[gw + 1];
    float4 D = *reinterpret_cast<const float4*>(ad + (size_t)gw * 4);
    float m0 = -1e30f, m1 = -1e30f, m2 = -1e30f, m3 = -1e30f;
    for (int j = beg + lane; j < end; j += 32) {
        int s = g_csrc[j];
        float4 A = *reinterpret_cast<const float4*>(as + (size_t)s * 4);
        float v0 = A.x + D.x, v1 = A.y + D.y, v2 = A.z + D.z, v3 = A.w + D.w;
        v0 = v0 > 0.f ? v0 : 0.2f * v0;
        v1 = v1 > 0.f ? v1 : 0.2f * v1;
        v2 = v2 > 0.f ? v2 : 0.2f * v2;
        v3 = v3 > 0.f ? v3 : 0.2f * v3;
        *reinterpret_cast<float4*>(g_alpha + (size_t)j * 4) = make_float4(v0, v1, v2, v3);
        m0 = fmaxf(m0, v0); m1 = fmaxf(m1, v1);
        m2 = fmaxf(m2, v2); m3 = fmaxf(m3, v3);
    }
#pragma unroll
    for (int o = 16; o; o >>= 1) {
        m0 = fmaxf(m0, __shfl_xor_sync(0xFFFFFFFFu, m0, o));
        m1 = fmaxf(m1, __shfl_xor_sync(0xFFFFFFFFu, m1, o));
        m2 = fmaxf(m2, __shfl_xor_sync(0xFFFFFFFFu, m2, o));
        m3 = fmaxf(m3, __shfl_xor_sync(0xFFFFFFFFu, m3, o));
    }
    float s0 = 0.f, s1 = 0.f, s2 = 0.f, s3 = 0.f;
    for (int j = beg + lane; j < end; j += 32) {
        float4 v = *reinterpret_cast<const float4*>(g_alpha + (size_t)j * 4);
        float x0 = expf(v.x - m0), x1 = expf(v.y - m1);
        float x2 = expf(v.z - m2), x3 = expf(v.w - m3);
        *reinterpret_cast<float4*>(g_alpha + (size_t)j * 4) = make_float4(x0, x1, x2, x3);
        s0 += x0; s1 += x1; s2 += x2; s3 += x3;
    }
#pragma unroll
    for (int o = 16; o; o >>= 1) {
        s0 += __shfl_xor_sync(0xFFFFFFFFu, s0, o);
        s1 += __shfl_xor_sync(0xFFFFFFFFu, s1, o);
        s2 += __shfl_xor_sync(0xFFFFFFFFu, s2, o);
        s3 += __shfl_xor_sync(0xFFFFFFFFu, s3, o);
    }
    if (lane == 0)
        *reinterpret_cast<float4*>(g_esum + (size_t)gw * 4) = make_float4(s0, s1, s2, s3);
}

// -------------------- layer-1 gather + bias/ELU + fused alpha2 --------------
__global__ __launch_bounds__(128) void agg1_k(const float* __restrict__ b1, int N)
{
    __shared__ float red[4][8];
    int n = blockIdx.x;
    if (n >= N) return;
    int tid = threadIdx.x, lane = tid & 31, wid = tid >> 5;
    int c = tid, h = c >> 5;
    int beg = g_off[n], end = g_off[n + 1];
    float r = 1.f / (g_esum[(size_t)n * 4 + h] + 1e-16f);
    float acc = 0.f;
    for (int j = beg; j < end; j++) {
        int s = g_csrc[j];
        float w = g_alpha[(size_t)j * 4 + h];
        acc = fmaf(w, g_h1[(size_t)s * 128 + c], acc);
    }
    float v = acc * r + b1[c];
    v = v > 0.f ? v : expm1f(v);
    g_hact[(size_t)n * 128 + c] = v;

    // fused alpha2: <hact[n], W2·a_{src,dst}2> per head (block reduction)
    float4 ws = *reinterpret_cast<const float4*>(&g_was[c * 4]);
    float4 wd = *reinterpret_cast<const float4*>(&g_wad[c * 4]);
    float p0 = v * ws.x, p1 = v * ws.y, p2 = v * ws.z, p3 = v * ws.w;
    float q0 = v * wd.x, q1 = v * wd.y, q2 = v * wd.z, q3 = v * wd.w;
#pragma unroll
    for (int o = 16; o; o >>= 1) {
        p0 += __shfl_xor_sync(0xFFFFFFFFu, p0, o);
        p1 += __shfl_xor_sync(0xFFFFFFFFu, p1, o);
        p2 += __shfl_xor_sync(0xFFFFFFFFu, p2, o);
        p3 += __shfl_xor_sync(0xFFFFFFFFu, p3, o);
        q0 += __shfl_xor_sync(0xFFFFFFFFu, q0, o);
        q1 += __shfl_xor_sync(0xFFFFFFFFu, q1, o);
        q2 += __shfl_xor_sync(0xFFFFFFFFu, q2, o);
        q3 += __shfl_xor_sync(0xFFFFFFFFu, q3, o);
    }
    if (lane == 0) {
        red[wid][0] = p0; red[wid][1] = p1; red[wid][2] = p2; red[wid][3] = p3;
        red[wid][4] = q0; red[wid][5] = q1; red[wid][6] = q2; red[wid][7] = q3;
    }
    __syncthreads();
    if (tid < 8) {
        float t = red[0][tid] + red[1][tid] + red[2][tid] + red[3][tid];
        if (tid < 4) g_as2[(size_t)n * 4 + tid] = t;
        else         g_ad2[(size_t)n * 4 + (tid - 4)] = t;
    }
}

// -------------------- layer-2 gather aggregate (of hact), normalized -------
__global__ __launch_bounds__(128) void agg2n_k(int N)
{
    int n = blockIdx.x;
    if (n >= N) return;
    int k = threadIdx.x;
    int beg = g_off[n], end = g_off[n + 1];
    float a0 = 0.f, a1 = 0.f, a2 = 0.f, a3 = 0.f;
    for (int j = beg; j < end; j++) {
        int s = g_csrc[j];
        float4 al = *reinterpret_cast<const float4*>(g_alpha + (size_t)j * 4);
        float v = g_hact[(size_t)s * 128 + k];
        a0 = fmaf(al.x, v, a0); a1 = fmaf(al.y, v, a1);
        a2 = fmaf(al.z, v, a2); a3 = fmaf(al.w, v, a3);
    }
    float4 es = *reinterpret_cast<const float4*>(g_esum + (size_t)n * 4);
    float* o = g_aggn + (size_t)n * 512;
    o[k]       = a0 * (0.25f / (es.x + 1e-16f));
    o[128 + k] = a1 * (0.25f / (es.y + 1e-16f));
    o[256 + k] = a2 * (0.25f / (es.z + 1e-16f));
    o[384 + k] = a3 * (0.25f / (es.w + 1e-16f));
}

// ---------------------------------------------------------------------------
extern "C" void kernel_launch(void* const* d_in, const int* in_sizes, int n_in,
                              void* d_out, int out_size)
{
    const float* x      = (const float*)d_in[0];
    const int*   eidx   = (const int*)d_in[1];
    const float* W1     = (const float*)d_in[2];
    const float* a_src1 = (const float*)d_in[3];
    const float* a_dst1 = (const float*)d_in[4];
    const float* b1     = (const float*)d_in[5];
    const float* W2     = (const float*)d_in[6];
    const float* a_src2 = (const float*)d_in[7];
    const float* a_dst2 = (const float*)d_in[8];
    const float* b2     = (const float*)d_in[9];
    const float* W_lin  = (const float*)d_in[10];
    const float* b_lin  = (const float*)d_in[11];

    const int N  = in_sizes[0] / 512;
    const int E  = in_sizes[1] / 2;
    const int Et = E + N;

    const int* src = eidx;
    const int* dst = eidx + E;

    float* out = (float*)d_out;
    float* emb = (float*)d_out + (size_t)N * 64;

    float* h1;   cudaGetSymbolAddress((void**)&h1,   g_h1);
    float* aggn; cudaGetSymbolAddress((void**)&aggn, g_aggn);
    int*   cnt;  cudaGetSymbolAddress((void**)&cnt,  g_cnt);
    float *as1p, *ad1p, *as2p, *ad2p;
    cudaGetSymbolAddress((void**)&as1p, g_as);  cudaGetSymbolAddress((void**)&ad1p, g_ad);
    cudaGetSymbolAddress((void**)&as2p, g_as2); cudaGetSymbolAddress((void**)&ad2p, g_ad2);
    __nv_bfloat16 *w1h, *w1l, *w2h, *w2l, *wlh, *wll;
    cudaGetSymbolAddress((void**)&w1h, g_W1h); cudaGetSymbolAddress((void**)&w1l, g_W1l);
    cudaGetSymbolAddress((void**)&w2h, g_W2h); cudaGetSymbolAddress((void**)&w2l, g_W2l);
    cudaGetSymbolAddress((void**)&wlh, g_WLh); cudaGetSymbolAddress((void**)&wll, g_WLl);

    const int T = 256;
    dim3 gg(1, (N + 127) / 128);

    int blk_e    = (Et + T - 1) / T;
    int blk_n    = (N + T - 1) / T;
    int blk_soft = (N * 32 + T - 1) / T;
    int NB       = (N + 1023) / 1024;

    // ---- CSR build ----
    cudaMemsetAsync(cnt, 0, (size_t)N * sizeof(int), 0);
    hist_k<<<blk_e, T>>>(dst, E, N);
    scan1<<<NB, 1024>>>(N);
    scan2<<<1, 1024>>>(NB);
    scan3<<<blk_n, T>>>(N, Et);
    scatter_k<<<blk_e, T>>>(src, dst, E, N);

    // ---- weight prep ----
    split_w<<<(512 * 128 + T - 1) / T, T>>>(W1, w1h, w1l, 512, 128);
    split_w2p<<<(512 * 128 + T - 1) / T, T>>>(W2);
    build_wa<<<64, T>>>(W2, a_src2, a_dst2);
    split_w<<<(128 * 64 + T - 1) / T, T>>>(W_lin, wlh, wll, 128, 64);

    // ---- layer 1 ----
    gemm_bf16x3<<<gg, T>>>(x, w1h, w1l, nullptr, h1, N, 128, 512, a_src1, a_dst1);
    edge_softmax<<<blk_soft, T>>>(as1p, ad1p, N);
    agg1_k<<<N, 128>>>(b1, N);

    // ---- layer 2 (deferred W2) ----
    edge_softmax<<<blk_soft, T>>>(as2p, ad2p, N);
    agg2n_k<<<N, 128>>>(N);
    gemm_bf16x3<<<gg, T>>>(aggn, w2h, w2l, b2, emb, N, 128, 512, nullptr, nullptr);

    // ---- head ----
    gemm_bf16x3<<<gg, T>>>(emb, wlh, wll, b_lin, out, N, 64, 128, nullptr, nullptr);
}

// round 11
// speedup vs baseline: 1.6536x; 1.1646x over previous
#include <cuda_runtime.h>
#include <cuda_bf16.h>
#include <cstdint>

// ---------------------------------------------------------------------------
// GATNet, round 11:
//  - round-10 base (CSR, deferred-W2, bf16x3 tensor GEMM + fused alpha1)
//  - NEW: warp-per-node fused softmax+aggregation kernels (softagg1/softagg2)
//    -> edge_softmax kernels and g_alpha/g_esum globals eliminated
//  - NEW: scan2 merged into scan3 (scan23)
// Output layout: [ out (N*64) | embeddings (N*128) ]
// ---------------------------------------------------------------------------

#define MAXN 100000
#define MAXE 600000
#define MAXET (MAXE + MAXN)
#define PAD 40

// -------------------- scratch (device globals; no allocs) ------------------
__device__ float g_h1[(size_t)MAXN * 128];
__device__ float g_hact[(size_t)MAXN * 128];
__device__ float g_aggn[(size_t)MAXN * 512];
__device__ float g_as[(size_t)MAXN * 4];    // layer-1 alpha_src
__device__ float g_ad[(size_t)MAXN * 4];    // layer-1 alpha_dst
__device__ float g_as2[(size_t)MAXN * 4];   // layer-2 alpha_src
__device__ float g_ad2[(size_t)MAXN * 4];   // layer-2 alpha_dst
__device__ int   g_cnt[MAXN];
__device__ int   g_off[MAXN + 1];
__device__ int   g_bsum[1024];
__device__ int   g_csrc[MAXET];
__device__ __nv_bfloat16 g_W1h[128 * 512],  g_W1l[128 * 512];
__device__ __nv_bfloat16 g_W2h[128 * 512],  g_W2l[128 * 512];
__device__ __nv_bfloat16 g_WLh[64 * 128],   g_WLl[64 * 128];
__device__ float g_was[128 * 4], g_wad[128 * 4];

// -------------------- asm helpers -------------------------------------------
__device__ __forceinline__ void mma16816(float* c, const uint32_t* a, const uint32_t* b) {
    asm volatile(
        "mma.sync.aligned.m16n8k16.row.col.f32.bf16.bf16.f32 "
        "{%0,%1,%2,%3}, {%4,%5,%6,%7}, {%8,%9}, {%0,%1,%2,%3};\n"
        : "+f"(c[0]), "+f"(c[1]), "+f"(c[2]), "+f"(c[3])
        : "r"(a[0]), "r"(a[1]), "r"(a[2]), "r"(a[3]), "r"(b[0]), "r"(b[1]));
}
__device__ __forceinline__ uint32_t smem_u32(const void* p) {
    return (uint32_t)__cvta_generic_to_shared(p);
}
__device__ __forceinline__ void ldsm4(uint32_t& r0, uint32_t& r1, uint32_t& r2,
                                      uint32_t& r3, uint32_t a) {
    asm volatile("ldmatrix.sync.aligned.m8n8.x4.shared.b16 {%0,%1,%2,%3}, [%4];"
                 : "=r"(r0), "=r"(r1), "=r"(r2), "=r"(r3) : "r"(a));
}
__device__ __forceinline__ void cpa16(uint32_t dst, const void* src, int srcsz) {
    asm volatile("cp.async.cg.shared.global [%0], [%1], 16, %2;"
                 :: "r"(dst), "l"(src), "r"(srcsz));
}
__device__ __forceinline__ void cpa_commit() { asm volatile("cp.async.commit_group;"); }
__device__ __forceinline__ void cpa_wait0()  { asm volatile("cp.async.wait_group 0;" ::: "memory"); }

__device__ __forceinline__ float leaky(float v) { return v > 0.f ? v : 0.2f * v; }

// -------------------- tensor GEMM + optional fused alpha1 epilogue ----------
__global__ __launch_bounds__(256) void gemm_bf16x3(
    const float* __restrict__ A,
    const __nv_bfloat16* __restrict__ Bth, const __nv_bfloat16* __restrict__ Btl,
    const float* __restrict__ bias, float* __restrict__ C,
    int M, int N, int K,
    const float* __restrict__ as1, const float* __restrict__ ad1)
{
    __shared__ __align__(16) __nv_bfloat16 Ah[2][128][PAD];
    __shared__ __align__(16) __nv_bfloat16 Al[2][128][PAD];
    __shared__ __align__(16) __nv_bfloat16 Bh[2][128][PAD];
    __shared__ __align__(16) __nv_bfloat16 Bl[2][128][PAD];

    const int tid  = threadIdx.x;
    const int lane = tid & 31;
    const int wid  = tid >> 5;
    const int brow = blockIdx.y * 128;
    const int bcol = blockIdx.x * 128;
    const int moff = (wid >> 2) * 64;
    const int noff = (wid & 3) * 32;

    float acc[4][4][4];
#pragma unroll
    for (int i = 0; i < 4; i++)
#pragma unroll
        for (int j = 0; j < 4; j++)
#pragma unroll
            for (int q = 0; q < 4; q++) acc[i][j][q] = 0.f;

    const int ar  = tid >> 1;
    const int ac  = (tid & 1) * 16;
    const int agr = min(brow + ar, M - 1);
    const float* aptr = A + (size_t)agr * K + ac;
    const int bn  = tid >> 1;
    const int bk  = (tid & 1) * 16;
    const bool bvalid = (bcol + bn) < N;
    const int bsz = bvalid ? 16 : 0;
    const int bnc = bvalid ? (bcol + bn) : 0;
    const __nv_bfloat16* bph0 = Bth + (size_t)bnc * K + bk;
    const __nv_bfloat16* bpl0 = Btl + (size_t)bnc * K + bk;

    const int lr = lane & 7;
    const int lj = lane >> 3;
    const int a_ro = ((lj & 1) << 3) + lr;
    const int a_co = ((lj >> 1) << 3);
    const int b_ro = ((lj >> 1) << 3) + lr;
    const int b_co = ((lj & 1) << 3);

    float4 avr[4];

    avr[0] = reinterpret_cast<const float4*>(aptr)[0];
    avr[1] = reinterpret_cast<const float4*>(aptr)[1];
    avr[2] = reinterpret_cast<const float4*>(aptr)[2];
    avr[3] = reinterpret_cast<const float4*>(aptr)[3];
    {
        uint32_t dh = smem_u32(&Bh[0][bn][bk]);
        uint32_t dl = smem_u32(&Bl[0][bn][bk]);
        cpa16(dh, bph0, bsz);      cpa16(dh + 16, bph0 + 8, bsz);
        cpa16(dl, bpl0, bsz);      cpa16(dl + 16, bpl0 + 8, bsz);
        cpa_commit();
    }
    {
        float av[16] = {avr[0].x, avr[0].y, avr[0].z, avr[0].w,
                        avr[1].x, avr[1].y, avr[1].z, avr[1].w,
                        avr[2].x, avr[2].y, avr[2].z, avr[2].w,
                        avr[3].x, avr[3].y, avr[3].z, avr[3].w};
        __nv_bfloat16 hb[16], lb[16];
#pragma unroll
        for (int i = 0; i < 16; i++) {
            hb[i] = __float2bfloat16(av[i]);
            lb[i] = __float2bfloat16(av[i] - __bfloat162float(hb[i]));
        }
        *reinterpret_cast<uint4*>(&Ah[0][ar][ac])     = *reinterpret_cast<uint4*>(hb);
        *reinterpret_cast<uint4*>(&Ah[0][ar][ac + 8]) = *reinterpret_cast<uint4*>(hb + 8);
        *reinterpret_cast<uint4*>(&Al[0][ar][ac])     = *reinterpret_cast<uint4*>(lb);
        *reinterpret_cast<uint4*>(&Al[0][ar][ac + 8]) = *reinterpret_cast<uint4*>(lb + 8);
    }
    cpa_wait0();
    __syncthreads();

    int p = 0;
    for (int k0 = 0; k0 < K; k0 += 32) {
        const bool nxt = (k0 + 32) < K;
        if (nxt) {
            const float* ap = aptr + k0 + 32;
            avr[0] = reinterpret_cast<const float4*>(ap)[0];
            avr[1] = reinterpret_cast<const float4*>(ap)[1];
            avr[2] = reinterpret_cast<const float4*>(ap)[2];
            avr[3] = reinterpret_cast<const float4*>(ap)[3];
            uint32_t dh = smem_u32(&Bh[p ^ 1][bn][bk]);
            uint32_t dl = smem_u32(&Bl[p ^ 1][bn][bk]);
            const __nv_bfloat16* bph = bph0 + k0 + 32;
            const __nv_bfloat16* bpl = bpl0 + k0 + 32;
            cpa16(dh, bph, bsz);      cpa16(dh + 16, bph + 8, bsz);
            cpa16(dl, bpl, bsz);      cpa16(dl + 16, bpl + 8, bsz);
            cpa_commit();
        }

#pragma unroll
        for (int ks = 0; ks < 32; ks += 16) {
            uint32_t bhf[4][2], blf[4][2];
            {
                uint32_t a0 = smem_u32(&Bh[p][noff + b_ro][ks + b_co]);
                uint32_t a1 = smem_u32(&Bh[p][noff + 16 + b_ro][ks + b_co]);
                uint32_t a2 = smem_u32(&Bl[p][noff + b_ro][ks + b_co]);
                uint32_t a3 = smem_u32(&Bl[p][noff + 16 + b_ro][ks + b_co]);
                ldsm4(bhf[0][0], bhf[0][1], bhf[1][0], bhf[1][1], a0);
                ldsm4(bhf[2][0], bhf[2][1], bhf[3][0], bhf[3][1], a1);
                ldsm4(blf[0][0], blf[0][1], blf[1][0], blf[1][1], a2);
                ldsm4(blf[2][0], blf[2][1], blf[3][0], blf[3][1], a3);
            }
#pragma unroll
            for (int im = 0; im < 4; im++) {
                uint32_t ahf[4], alf[4];
                uint32_t aa  = smem_u32(&Ah[p][moff + im * 16 + a_ro][ks + a_co]);
                uint32_t al_ = smem_u32(&Al[p][moff + im * 16 + a_ro][ks + a_co]);
                ldsm4(ahf[0], ahf[1], ahf[2], ahf[3], aa);
                ldsm4(alf[0], alf[1], alf[2], alf[3], al_);
#pragma unroll
                for (int in = 0; in < 4; in++) {
                    mma16816(acc[im][in], ahf, bhf[in]);
                    mma16816(acc[im][in], ahf, blf[in]);
                    mma16816(acc[im][in], alf, bhf[in]);
                }
            }
        }

        if (nxt) {
            float av[16] = {avr[0].x, avr[0].y, avr[0].z, avr[0].w,
                            avr[1].x, avr[1].y, avr[1].z, avr[1].w,
                            avr[2].x, avr[2].y, avr[2].z, avr[2].w,
                            avr[3].x, avr[3].y, avr[3].z, avr[3].w};
            __nv_bfloat16 hb[16], lb[16];
#pragma unroll
            for (int i = 0; i < 16; i++) {
                hb[i] = __float2bfloat16(av[i]);
                lb[i] = __float2bfloat16(av[i] - __bfloat162float(hb[i]));
            }
            *reinterpret_cast<uint4*>(&Ah[p ^ 1][ar][ac])     = *reinterpret_cast<uint4*>(hb);
            *reinterpret_cast<uint4*>(&Ah[p ^ 1][ar][ac + 8]) = *reinterpret_cast<uint4*>(hb + 8);
            *reinterpret_cast<uint4*>(&Al[p ^ 1][ar][ac])     = *reinterpret_cast<uint4*>(lb);
            *reinterpret_cast<uint4*>(&Al[p ^ 1][ar][ac + 8]) = *reinterpret_cast<uint4*>(lb + 8);
            cpa_wait0();
        }
        __syncthreads();
        p ^= 1;
    }

    // ---- C epilogue ----
#pragma unroll
    for (int im = 0; im < 4; im++) {
#pragma unroll
        for (int in = 0; in < 4; in++) {
            int gr = brow + moff + im * 16 + (lane >> 2);
            int gc = bcol + noff + in * 8 + (lane & 3) * 2;
            if (gc >= N) continue;
            float bx = bias ? bias[gc] : 0.f;
            float by = bias ? bias[gc + 1] : 0.f;
            if (gr < M) {
                float2 v = make_float2(acc[im][in][0] + bx, acc[im][in][1] + by);
                *reinterpret_cast<float2*>(C + (size_t)gr * N + gc) = v;
            }
            if (gr + 8 < M) {
                float2 v = make_float2(acc[im][in][2] + bx, acc[im][in][3] + by);
                *reinterpret_cast<float2*>(C + (size_t)(gr + 8) * N + gc) = v;
            }
        }
    }

    // ---- fused alpha1 epilogue (layer-1 GEMM only; N==128, bcol==0) ----
    if (as1) {
        const int head = wid & 3;
#pragma unroll
        for (int im = 0; im < 4; im++) {
            float s0 = 0.f, s1 = 0.f, d0 = 0.f, d1 = 0.f;
#pragma unroll
            for (int in = 0; in < 4; in++) {
                int gc = noff + in * 8 + (lane & 3) * 2;
                float a0 = as1[gc], a1 = as1[gc + 1];
                float e0 = ad1[gc], e1 = ad1[gc + 1];
                s0 += acc[im][in][0] * a0 + acc[im][in][1] * a1;
                s1 += acc[im][in][2] * a0 + acc[im][in][3] * a1;
                d0 += acc[im][in][0] * e0 + acc[im][in][1] * e1;
                d1 += acc[im][in][2] * e0 + acc[im][in][3] * e1;
            }
#pragma unroll
            for (int o = 1; o < 4; o <<= 1) {
                s0 += __shfl_xor_sync(0xFFFFFFFFu, s0, o);
                s1 += __shfl_xor_sync(0xFFFFFFFFu, s1, o);
                d0 += __shfl_xor_sync(0xFFFFFFFFu, d0, o);
                d1 += __shfl_xor_sync(0xFFFFFFFFu, d1, o);
            }
            if ((lane & 3) == 0) {
                int gr = brow + moff + im * 16 + (lane >> 2);
                if (gr < M)     { g_as[(size_t)gr * 4 + head] = s0; g_ad[(size_t)gr * 4 + head] = d0; }
                if (gr + 8 < M) { g_as[(size_t)(gr + 8) * 4 + head] = s1; g_ad[(size_t)(gr + 8) * 4 + head] = d1; }
            }
        }
    }
}

// -------------------- weight prep kernels ----------------------------------
__global__ void split_w(const float* __restrict__ W,
                        __nv_bfloat16* __restrict__ hi, __nv_bfloat16* __restrict__ lo,
                        int K, int N)
{
    int idx = blockIdx.x * blockDim.x + threadIdx.x;
    if (idx >= K * N) return;
    int k = idx / N, n = idx % N;
    float v = W[idx];
    __nv_bfloat16 h = __float2bfloat16(v);
    hi[(size_t)n * K + k] = h;
    lo[(size_t)n * K + k] = __float2bfloat16(v - __bfloat162float(h));
}
__global__ void split_w2p(const float* __restrict__ W2)
{
    int idx = blockIdx.x * blockDim.x + threadIdx.x;
    if (idx >= 512 * 128) return;
    int row = idx >> 7, c = idx & 127;
    int h = row >> 7, k = row & 127;
    float v = W2[(size_t)k * 512 + h * 128 + c];
    __nv_bfloat16 hb = __float2bfloat16(v);
    g_W2h[(size_t)c * 512 + row] = hb;
    g_W2l[(size_t)c * 512 + row] = __float2bfloat16(v - __bfloat162float(hb));
}
__global__ void build_wa(const float* __restrict__ W2,
                         const float* __restrict__ as2, const float* __restrict__ ad2)
{
    int gw   = (blockIdx.x * blockDim.x + threadIdx.x) >> 5;
    int lane = threadIdx.x & 31;
    if (gw >= 512) return;
    int k = gw >> 2, h = gw & 3;
    float ss = 0.f, sd = 0.f;
    for (int c = lane; c < 128; c += 32) {
        float w = W2[(size_t)k * 512 + h * 128 + c];
        ss = fmaf(w, as2[h * 128 + c], ss);
        sd = fmaf(w, ad2[h * 128 + c], sd);
    }
#pragma unroll
    for (int o = 16; o; o >>= 1) {
        ss += __shfl_xor_sync(0xFFFFFFFFu, ss, o);
        sd += __shfl_xor_sync(0xFFFFFFFFu, sd, o);
    }
    if (lane == 0) { g_was[k * 4 + h] = ss; g_wad[k * 4 + h] = sd; }
}

// -------------------- CSR build --------------------------------------------
__global__ void hist_k(const int* __restrict__ dst, int E, int N) {
    int e = blockIdx.x * blockDim.x + threadIdx.x;
    if (e >= E + N) return;
    int d = (e < E) ? dst[e] : e - E;
    atomicAdd(&g_cnt[d], 1);
}
__global__ __launch_bounds__(1024) void scan1(int N) {
    __shared__ int sh[1024];
    int i = blockIdx.x * 1024 + threadIdx.x;
    int v = (i < N) ? g_cnt[i] : 0;
    sh[threadIdx.x] = v;
    __syncthreads();
    for (int o = 1; o < 1024; o <<= 1) {
        int t = (threadIdx.x >= o) ? sh[threadIdx.x - o] : 0;
        __syncthreads();
        sh[threadIdx.x] += t;
        __syncthreads();
    }
    if (i < N) g_off[i] = sh[threadIdx.x] - v;
    if (threadIdx.x == 1023) g_bsum[blockIdx.x] = sh[1023];
}
// merged scan2+scan3: every block redundantly scans block sums (NB<=128)
__global__ void scan23(int N, int Et, int NB) {
    __shared__ int sb[128];
    int t = threadIdx.x;
    if (t < 128) sb[t] = (t < NB) ? g_bsum[t] : 0;
    __syncthreads();
    for (int o = 1; o < 128; o <<= 1) {
        int v = (t < 128 && t >= o) ? sb[t - o] : 0;
        __syncthreads();
        if (t < 128) sb[t] += v;
        __syncthreads();
    }
    int i = blockIdx.x * blockDim.x + t;
    if (i < N) {
        int b = i >> 10;
        int add = (b == 0) ? 0 : sb[b - 1];
        int v = g_off[i] + add;
        g_off[i] = v;
        g_cnt[i] = v;
    }
    if (i == 0) g_off[N] = Et;
}
__global__ void scatter_k(const int* __restrict__ src, const int* __restrict__ dst,
                          int E, int N) {
    int e = blockIdx.x * blockDim.x + threadIdx.x;
    if (e >= E + N) return;
    int s, d;
    if (e < E) { s = src[e]; d = dst[e]; } else { s = d = e - E; }
    int p = atomicAdd(&g_cnt[d], 1);
    g_csrc[p] = s;
}

// -------------------- fused softmax + aggregation, layer 1 ------------------
// Warp per node. Softmax over incoming edges in registers (edge j -> lane j,
// exact recompute path for deg>32). Aggregates h1, bias+ELU -> hact, then
// fused alpha2 reduction (as2/ad2).
__global__ __launch_bounds__(256) void softagg1(const float* __restrict__ b1, int N)
{
    int warp = (blockIdx.x * blockDim.x + threadIdx.x) >> 5;
    int lane = threadIdx.x & 31;
    if (warp >= N) return;
    int n = warp;
    int beg = g_off[n], end = g_off[n + 1], deg = end - beg;
    float4 D = *reinterpret_cast<const float4*>(g_ad + (size_t)n * 4);

    // first-chunk logits in registers
    int   sj = 0;
    float v0 = -1e30f, v1 = -1e30f, v2 = -1e30f, v3 = -1e30f;
    if (lane < deg) {
        sj = g_csrc[beg + lane];
        float4 A = *reinterpret_cast<const float4*>(g_as + (size_t)sj * 4);
        v0 = leaky(A.x + D.x); v1 = leaky(A.y + D.y);
        v2 = leaky(A.z + D.z); v3 = leaky(A.w + D.w);
    }
    float m0 = v0, m1 = v1, m2 = v2, m3 = v3;
    for (int j = beg + 32 + lane; j < end; j += 32) {       // rare overflow path
        int s = g_csrc[j];
        float4 A = *reinterpret_cast<const float4*>(g_as + (size_t)s * 4);
        m0 = fmaxf(m0, leaky(A.x + D.x)); m1 = fmaxf(m1, leaky(A.y + D.y));
        m2 = fmaxf(m2, leaky(A.z + D.z)); m3 = fmaxf(m3, leaky(A.w + D.w));
    }
#pragma unroll
    for (int o = 16; o; o >>= 1) {
        m0 = fmaxf(m0, __shfl_xor_sync(0xFFFFFFFFu, m0, o));
        m1 = fmaxf(m1, __shfl_xor_sync(0xFFFFFFFFu, m1, o));
        m2 = fmaxf(m2, __shfl_xor_sync(0xFFFFFFFFu, m2, o));
        m3 = fmaxf(m3, __shfl_xor_sync(0xFFFFFFFFu, m3, o));
    }
    float e0 = (lane < deg) ? expf(v0 - m0) : 0.f;
    float e1 = (lane < deg) ? expf(v1 - m1) : 0.f;
    float e2 = (lane < deg) ? expf(v2 - m2) : 0.f;
    float e3 = (lane < deg) ? expf(v3 - m3) : 0.f;
    float s0 = e0, s1 = e1, s2 = e2, s3 = e3;
    for (int j = beg + 32 + lane; j < end; j += 32) {
        int s = g_csrc[j];
        float4 A = *reinterpret_cast<const float4*>(g_as + (size_t)s * 4);
        s0 += expf(leaky(A.x + D.x) - m0); s1 += expf(leaky(A.y + D.y) - m1);
        s2 += expf(leaky(A.z + D.z) - m2); s3 += expf(leaky(A.w + D.w) - m3);
    }
#pragma unroll
    for (int o = 16; o; o >>= 1) {
        s0 += __shfl_xor_sync(0xFFFFFFFFu, s0, o);
        s1 += __shfl_xor_sync(0xFFFFFFFFu, s1, o);
        s2 += __shfl_xor_sync(0xFFFFFFFFu, s2, o);
        s3 += __shfl_xor_sync(0xFFFFFFFFu, s3, o);
    }
    float r0 = 1.f / (s0 + 1e-16f), r1 = 1.f / (s1 + 1e-16f);
    float r2 = 1.f / (s2 + 1e-16f), r3 = 1.f / (s3 + 1e-16f);

    // aggregation: lane covers features lane, lane+32, lane+64, lane+96
    float a0 = 0.f, a1 = 0.f, a2 = 0.f, a3 = 0.f;
    for (int j = 0; j < deg; j++) {
        int s; float w0, w1, w2, w3;
        if (j < 32) {
            s  = __shfl_sync(0xFFFFFFFFu, sj, j);
            w0 = __shfl_sync(0xFFFFFFFFu, e0, j);
            w1 = __shfl_sync(0xFFFFFFFFu, e1, j);
            w2 = __shfl_sync(0xFFFFFFFFu, e2, j);
            w3 = __shfl_sync(0xFFFFFFFFu, e3, j);
        } else {
            s = g_csrc[beg + j];
            float4 A = *reinterpret_cast<const float4*>(g_as + (size_t)s * 4);
            w0 = expf(leaky(A.x + D.x) - m0); w1 = expf(leaky(A.y + D.y) - m1);
            w2 = expf(leaky(A.z + D.z) - m2); w3 = expf(leaky(A.w + D.w) - m3);
        }
        const float* row = g_h1 + (size_t)s * 128;
        a0 = fmaf(w0, row[lane],      a0);
        a1 = fmaf(w1, row[lane + 32], a1);
        a2 = fmaf(w2, row[lane + 64], a2);
        a3 = fmaf(w3, row[lane + 96], a3);
    }
    float h0 = a0 * r0 + b1[lane];
    float h1v = a1 * r1 + b1[lane + 32];
    float h2 = a2 * r2 + b1[lane + 64];
    float h3 = a3 * r3 + b1[lane + 96];
    h0 = h0 > 0.f ? h0 : expm1f(h0);
    h1v = h1v > 0.f ? h1v : expm1f(h1v);
    h2 = h2 > 0.f ? h2 : expm1f(h2);
    h3 = h3 > 0.f ? h3 : expm1f(h3);
    float* hr = g_hact + (size_t)n * 128;
    hr[lane] = h0; hr[lane + 32] = h1v; hr[lane + 64] = h2; hr[lane + 96] = h3;

    // fused alpha2: <hact[n], W2·a_{src,dst}2> per head
    float4 ws0 = *reinterpret_cast<const float4*>(&g_was[lane * 4]);
    float4 ws1 = *reinterpret_cast<const float4*>(&g_was[(lane + 32) * 4]);
    float4 ws2 = *reinterpret_cast<const float4*>(&g_was[(lane + 64) * 4]);
    float4 ws3 = *reinterpret_cast<const float4*>(&g_was[(lane + 96) * 4]);
    float4 wd0 = *reinterpret_cast<const float4*>(&g_wad[lane * 4]);
    float4 wd1 = *reinterpret_cast<const float4*>(&g_wad[(lane + 32) * 4]);
    float4 wd2 = *reinterpret_cast<const float4*>(&g_wad[(lane + 64) * 4]);
    float4 wd3 = *reinterpret_cast<const float4*>(&g_wad[(lane + 96) * 4]);
    float p0 = h0 * ws0.x + h1v * ws1.x + h2 * ws2.x + h3 * ws3.x;
    float p1 = h0 * ws0.y + h1v * ws1.y + h2 * ws2.y + h3 * ws3.y;
    float p2 = h0 * ws0.z + h1v * ws1.z + h2 * ws2.z + h3 * ws3.z;
    float p3 = h0 * ws0.w + h1v * ws1.w + h2 * ws2.w + h3 * ws3.w;
    float q0 = h0 * wd0.x + h1v * wd1.x + h2 * wd2.x + h3 * wd3.x;
    float q1 = h0 * wd0.y + h1v * wd1.y + h2 * wd2.y + h3 * wd3.y;
    float q2 = h0 * wd0.z + h1v * wd1.z + h2 * wd2.z + h3 * wd3.z;
    float q3 = h0 * wd0.w + h1v * wd1.w + h2 * wd2.w + h3 * wd3.w;
#pragma unroll
    for (int o = 16; o; o >>= 1) {
        p0 += __shfl_xor_sync(0xFFFFFFFFu, p0, o);
        p1 += __shfl_xor_sync(0xFFFFFFFFu, p1, o);
        p2 += __shfl_xor_sync(0xFFFFFFFFu, p2, o);
        p3 += __shfl_xor_sync(0xFFFFFFFFu, p3, o);
        q0 += __shfl_xor_sync(0xFFFFFFFFu, q0, o);
        q1 += __shfl_xor_sync(0xFFFFFFFFu, q1, o);
        q2 += __shfl_xor_sync(0xFFFFFFFFu, q2, o);
        q3 += __shfl_xor_sync(0xFFFFFFFFu, q3, o);
    }
    if (lane == 0) {
        *reinterpret_cast<float4*>(&g_as2[(size_t)n * 4]) = make_float4(p0, p1, p2, p3);
        *reinterpret_cast<float4*>(&g_ad2[(size_t)n * 4]) = make_float4(q0, q1, q2, q3);
    }
}

// -------------------- fused softmax + aggregation, layer 2 ------------------
__global__ __launch_bounds__(256) void softagg2(int N)
{
    int warp = (blockIdx.x * blockDim.x + threadIdx.x) >> 5;
    int lane = threadIdx.x & 31;
    if (warp >= N) return;
    int n = warp;
    int beg = g_off[n], end = g_off[n + 1], deg = end - beg;
    float4 D = *reinterpret_cast<const float4*>(g_ad2 + (size_t)n * 4);

    int   sj = 0;
    float v0 = -1e30f, v1 = -1e30f, v2 = -1e30f, v3 = -1e30f;
    if (lane < deg) {
        sj = g_csrc[beg + lane];
        float4 A = *reinterpret_cast<const float4*>(g_as2 + (size_t)sj * 4);
        v0 = leaky(A.x + D.x); v1 = leaky(A.y + D.y);
        v2 = leaky(A.z + D.z); v3 = leaky(A.w + D.w);
    }
    float m0 = v0, m1 = v1, m2 = v2, m3 = v3;
    for (int j = beg + 32 + lane; j < end; j += 32) {
        int s = g_csrc[j];
        float4 A = *reinterpret_cast<const float4*>(g_as2 + (size_t)s * 4);
        m0 = fmaxf(m0, leaky(A.x + D.x)); m1 = fmaxf(m1, leaky(A.y + D.y));
        m2 = fmaxf(m2, leaky(A.z + D.z)); m3 = fmaxf(m3, leaky(A.w + D.w));
    }
#pragma unroll
    for (int o = 16; o; o >>= 1) {
        m0 = fmaxf(m0, __shfl_xor_sync(0xFFFFFFFFu, m0, o));
        m1 = fmaxf(m1, __shfl_xor_sync(0xFFFFFFFFu, m1, o));
        m2 = fmaxf(m2, __shfl_xor_sync(0xFFFFFFFFu, m2, o));
        m3 = fmaxf(m3, __shfl_xor_sync(0xFFFFFFFFu, m3, o));
    }
    float e0 = (lane < deg) ? expf(v0 - m0) : 0.f;
    float e1 = (lane < deg) ? expf(v1 - m1) : 0.f;
    float e2 = (lane < deg) ? expf(v2 - m2) : 0.f;
    float e3 = (lane < deg) ? expf(v3 - m3) : 0.f;
    float s0 = e0, s1 = e1, s2 = e2, s3 = e3;
    for (int j = beg + 32 + lane; j < end; j += 32) {
        int s = g_csrc[j];
        float4 A = *reinterpret_cast<const float4*>(g_as2 + (size_t)s * 4);
        s0 += expf(leaky(A.x + D.x) - m0); s1 += expf(leaky(A.y + D.y) - m1);
        s2 += expf(leaky(A.z + D.z) - m2); s3 += expf(leaky(A.w + D.w) - m3);
    }
#pragma unroll
    for (int o = 16; o; o >>= 1) {
        s0 += __shfl_xor_sync(0xFFFFFFFFu, s0, o);
        s1 += __shfl_xor_sync(0xFFFFFFFFu, s1, o);
        s2 += __shfl_xor_sync(0xFFFFFFFFu, s2, o);
        s3 += __shfl_xor_sync(0xFFFFFFFFu, s3, o);
    }
    float r0 = 0.25f / (s0 + 1e-16f), r1 = 0.25f / (s1 + 1e-16f);
    float r2 = 0.25f / (s2 + 1e-16f), r3 = 0.25f / (s3 + 1e-16f);

    // aggregation: 16 accumulators = 4 heads x 4 feature quarters
    float acc[4][4];
#pragma unroll
    for (int h = 0; h < 4; h++)
#pragma unroll
        for (int q = 0; q < 4; q++) acc[h][q] = 0.f;

    for (int j = 0; j < deg; j++) {
        int s; float w0, w1, w2, w3;
        if (j < 32) {
            s  = __shfl_sync(0xFFFFFFFFu, sj, j);
            w0 = __shfl_sync(0xFFFFFFFFu, e0, j);
            w1 = __shfl_sync(0xFFFFFFFFu, e1, j);
            w2 = __shfl_sync(0xFFFFFFFFu, e2, j);
            w3 = __shfl_sync(0xFFFFFFFFu, e3, j);
        } else {
            s = g_csrc[beg + j];
            float4 A = *reinterpret_cast<const float4*>(g_as2 + (size_t)s * 4);
            w0 = expf(leaky(A.x + D.x) - m0); w1 = expf(leaky(A.y + D.y) - m1);
            w2 = expf(leaky(A.z + D.z) - m2); w3 = expf(leaky(A.w + D.w) - m3);
        }
        const float* row = g_hact + (size_t)s * 128;
        float hv0 = row[lane], hv1 = row[lane + 32];
        float hv2 = row[lane + 64], hv3 = row[lane + 96];
        acc[0][0] = fmaf(w0, hv0, acc[0][0]); acc[0][1] = fmaf(w0, hv1, acc[0][1]);
        acc[0][2] = fmaf(w0, hv2, acc[0][2]); acc[0][3] = fmaf(w0, hv3, acc[0][3]);
        acc[1][0] = fmaf(w1, hv0, acc[1][0]); acc[1][1] = fmaf(w1, hv1, acc[1][1]);
        acc[1][2] = fmaf(w1, hv2, acc[1][2]); acc[1][3] = fmaf(w1, hv3, acc[1][3]);
        acc[2][0] = fmaf(w2, hv0, acc[2][0]); acc[2][1] = fmaf(w2, hv1, acc[2][1]);
        acc[2][2] = fmaf(w2, hv2, acc[2][2]); acc[2][3] = fmaf(w2, hv3, acc[2][3]);
        acc[3][0] = fmaf(w3, hv0, acc[3][0]); acc[3][1] = fmaf(w3, hv1, acc[3][1]);
        acc[3][2] = fmaf(w3, hv2, acc[3][2]); acc[3][3] = fmaf(w3, hv3, acc[3][3]);
    }
    float* o = g_aggn + (size_t)n * 512;
    float rr[4] = {r0, r1, r2, r3};
#pragma unroll
    for (int h = 0; h < 4; h++) {
        o[h * 128 + lane]      = acc[h][0] * rr[h];
        o[h * 128 + lane + 32] = acc[h][1] * rr[h];
        o[h * 128 + lane + 64] = acc[h][2] * rr[h];
        o[h * 128 + lane + 96] = acc[h][3] * rr[h];
    }
}

// ---------------------------------------------------------------------------
extern "C" void kernel_launch(void* const* d_in, const int* in_sizes, int n_in,
                              void* d_out, int out_size)
{
    const float* x      = (const float*)d_in[0];
    const int*   eidx   = (const int*)d_in[1];
    const float* W1     = (const float*)d_in[2];
    const float* a_src1 = (const float*)d_in[3];
    const float* a_dst1 = (const float*)d_in[4];
    const float* b1     = (const float*)d_in[5];
    const float* W2     = (const float*)d_in[6];
    const float* a_src2 = (const float*)d_in[7];
    const float* a_dst2 = (const float*)d_in[8];
    const float* b2     = (const float*)d_in[9];
    const float* W_lin  = (const float*)d_in[10];
    const float* b_lin  = (const float*)d_in[11];

    const int N  = in_sizes[0] / 512;
    const int E  = in_sizes[1] / 2;
    const int Et = E + N;

    const int* src = eidx;
    const int* dst = eidx + E;

    float* out = (float*)d_out;
    float* emb = (float*)d_out + (size_t)N * 64;

    float* h1;   cudaGetSymbolAddress((void**)&h1,   g_h1);
    float* aggn; cudaGetSymbolAddress((void**)&aggn, g_aggn);
    int*   cnt;  cudaGetSymbolAddress((void**)&cnt,  g_cnt);
    __nv_bfloat16 *w1h, *w1l, *w2h, *w2l, *wlh, *wll;
    cudaGetSymbolAddress((void**)&w1h, g_W1h); cudaGetSymbolAddress((void**)&w1l, g_W1l);
    cudaGetSymbolAddress((void**)&w2h, g_W2h); cudaGetSymbolAddress((void**)&w2l, g_W2l);
    cudaGetSymbolAddress((void**)&wlh, g_WLh); cudaGetSymbolAddress((void**)&wll, g_WLl);

    const int T = 256;
    dim3 gg(1, (N + 127) / 128);

    int blk_e  = (Et + T - 1) / T;
    int blk_n  = (N + T - 1) / T;
    int blk_wn = (N * 32 + T - 1) / T;   // warp-per-node kernels
    int NB     = (N + 1023) / 1024;

    // ---- CSR build ----
    cudaMemsetAsync(cnt, 0, (size_t)N * sizeof(int), 0);
    hist_k<<<blk_e, T>>>(dst, E, N);
    scan1<<<NB, 1024>>>(N);
    scan23<<<blk_n, T>>>(N, Et, NB);
    scatter_k<<<blk_e, T>>>(src, dst, E, N);

    // ---- weight prep ----
    split_w<<<(512 * 128 + T - 1) / T, T>>>(W1, w1h, w1l, 512, 128);
    split_w2p<<<(512 * 128 + T - 1) / T, T>>>(W2);
    build_wa<<<64, T>>>(W2, a_src2, a_dst2);
    split_w<<<(128 * 64 + T - 1) / T, T>>>(W_lin, wlh, wll, 128, 64);

    // ---- layer 1: GEMM (+fused alpha1), fused softmax+agg (+fused alpha2) --
    gemm_bf16x3<<<gg, T>>>(x, w1h, w1l, nullptr, h1, N, 128, 512, a_src1, a_dst1);
    softagg1<<<blk_wn, T>>>(b1, N);

    // ---- layer 2: fused softmax+agg, GEMM (deferred W2) ----
    softagg2<<<blk_wn, T>>>(N);
    gemm_bf16x3<<<gg, T>>>(aggn, w2h, w2l, b2, emb, N, 128, 512, nullptr, nullptr);

    // ---- head ----
    gemm_bf16x3<<<gg, T>>>(emb, wlh, wll, b_lin, out, N, 64, 128, nullptr, nullptr);
}